// round 2
// baseline (speedup 1.0000x reference)
#include <cuda_runtime.h>
#include <cstdint>

#define HIDDEN 128
#define MAX_NODES 50000
#define MAX_EDGES 500000

// Scratch (static __device__ arrays — no allocation allowed).
__device__ float g_learn1[MAX_NODES * HIDDEN];     // layer-1 output (incl. bias0)
__device__ int   g_counts[MAX_NODES];              // per-row edge counts
__device__ int   g_offsets[MAX_NODES + 1];         // CSR row offsets
__device__ int   g_cursor[MAX_NODES];              // permute cursors (copy of offsets)
__device__ int2  g_edges[MAX_EDGES];               // row-sorted (col, val-bits) pairs

// ---------------------------------------------------------------------------
// 1) zero per-row counts
// ---------------------------------------------------------------------------
__global__ void zero_counts_kernel(int* __restrict__ counts, int n) {
    int i = blockIdx.x * blockDim.x + threadIdx.x;
    if (i < n) counts[i] = 0;
}

// ---------------------------------------------------------------------------
// 2) histogram of destination rows
// ---------------------------------------------------------------------------
__global__ void hist_kernel(const int* __restrict__ row, int* __restrict__ counts,
                            int n_edges) {
    int e = blockIdx.x * blockDim.x + threadIdx.x;
    if (e < n_edges) atomicAdd(&counts[__ldg(row + e)], 1);
}

// ---------------------------------------------------------------------------
// 3) single-block exclusive scan of counts -> offsets (+ cursor copy)
//    1024 threads, each handles a contiguous chunk serially; Hillis-Steele
//    block scan of the 1024 chunk sums.
// ---------------------------------------------------------------------------
__global__ void scan_kernel(const int* __restrict__ counts,
                            int* __restrict__ offsets,
                            int* __restrict__ cursor, int n) {
    const int T = 1024;
    __shared__ int s[T];
    int t = threadIdx.x;
    int items = (n + T - 1) / T;
    int start = t * items;
    int end = min(start + items, n);

    int sum = 0;
    for (int i = start; i < end; i++) sum += counts[i];
    s[t] = sum;
    __syncthreads();

    // inclusive Hillis-Steele scan
    for (int off = 1; off < T; off <<= 1) {
        int v = (t >= off) ? s[t - off] : 0;
        __syncthreads();
        s[t] += v;
        __syncthreads();
    }

    int run = (t > 0) ? s[t - 1] : 0;   // exclusive prefix for this chunk
    for (int i = start; i < end; i++) {
        offsets[i] = run;
        cursor[i]  = run;
        run += counts[i];
    }
    if (t == T - 1) offsets[n] = s[T - 1];
}

// ---------------------------------------------------------------------------
// 4) permute edges into row-grouped order as packed (col, val-bits)
// ---------------------------------------------------------------------------
__global__ void permute_kernel(const int* __restrict__ row,
                               const int* __restrict__ col,
                               const float* __restrict__ val,
                               int* __restrict__ cursor,
                               int2* __restrict__ edges, int n_edges) {
    int e = blockIdx.x * blockDim.x + threadIdx.x;
    if (e >= n_edges) return;
    int r = __ldg(row + e);
    int p = atomicAdd(&cursor[r], 1);
    edges[p] = make_int2(__ldg(col + e), __float_as_int(__ldg(val + e)));
}

// ---------------------------------------------------------------------------
// 5) CSR SpMM, one warp per destination row, register accumulation.
//    FUSE_FINAL=0:  y[r] = sum(val * x[col]) + bias_row
//    FUSE_FINAL=1:  y[r] = (fea[r] + x[r] + (sum + bias_row)) / 3
//    (layer 2: x == learn1, so x[r] is the residual learn1 term)
// ---------------------------------------------------------------------------
template <int FUSE_FINAL>
__global__ void spmm_csr_kernel(const float4* __restrict__ x,
                                float4* __restrict__ y,
                                const int* __restrict__ offsets,
                                const int2* __restrict__ edges,
                                const float4* __restrict__ bias4,  // 32 float4
                                const float4* __restrict__ fea,    // residual (layer 2)
                                int n_nodes) {
    int gtid = blockIdx.x * blockDim.x + threadIdx.x;
    int r = gtid >> 5;
    if (r >= n_nodes) return;
    int lane = threadIdx.x & 31;

    float4 acc = __ldg(bias4 + lane);

    int beg = __ldg(offsets + r);
    int end = __ldg(offsets + r + 1);

    int i = beg;
    // unroll-by-2 for memory-level parallelism on the gathers
    for (; i + 1 < end; i += 2) {
        int2 e0 = __ldg(edges + i);
        int2 e1 = __ldg(edges + i + 1);
        float v0 = __int_as_float(e0.y);
        float v1 = __int_as_float(e1.y);
        float4 x0 = __ldg(x + (size_t)e0.x * 32 + lane);
        float4 x1 = __ldg(x + (size_t)e1.x * 32 + lane);
        acc.x += v0 * x0.x; acc.y += v0 * x0.y; acc.z += v0 * x0.z; acc.w += v0 * x0.w;
        acc.x += v1 * x1.x; acc.y += v1 * x1.y; acc.z += v1 * x1.z; acc.w += v1 * x1.w;
    }
    if (i < end) {
        int2 e0 = __ldg(edges + i);
        float v0 = __int_as_float(e0.y);
        float4 x0 = __ldg(x + (size_t)e0.x * 32 + lane);
        acc.x += v0 * x0.x; acc.y += v0 * x0.y; acc.z += v0 * x0.z; acc.w += v0 * x0.w;
    }

    size_t idx = (size_t)r * 32 + lane;
    if (FUSE_FINAL) {
        const float inv3 = 1.0f / 3.0f;
        float4 f  = __ldg(fea + idx);
        float4 l1 = __ldg(x + idx);      // x == learn1 here
        acc.x = (f.x + l1.x + acc.x) * inv3;
        acc.y = (f.y + l1.y + acc.y) * inv3;
        acc.z = (f.z + l1.z + acc.z) * inv3;
        acc.w = (f.w + l1.w + acc.w) * inv3;
    }
    y[idx] = acc;
}

extern "C" void kernel_launch(void* const* d_in, const int* in_sizes, int n_in,
                              void* d_out, int out_size) {
    const float* fea     = (const float*)d_in[0];   // [N, 128]
    const int*   adj_row = (const int*)  d_in[1];   // [E]
    const int*   adj_col = (const int*)  d_in[2];   // [E]
    const float* adj_val = (const float*)d_in[3];   // [E]
    const float* bias    = (const float*)d_in[4];   // [2, 128]

    int n_edges = in_sizes[1];
    int n_nodes = in_sizes[0] / HIDDEN;

    float* learn1; cudaGetSymbolAddress((void**)&learn1, g_learn1);
    int*   counts; cudaGetSymbolAddress((void**)&counts, g_counts);
    int*   offs;   cudaGetSymbolAddress((void**)&offs,   g_offsets);
    int*   cursor; cudaGetSymbolAddress((void**)&cursor, g_cursor);
    int2*  edges;  cudaGetSymbolAddress((void**)&edges,  g_edges);
    float* out = (float*)d_out;

    const int TPB = 256;

    // 1) zero counts
    zero_counts_kernel<<<(n_nodes + TPB - 1) / TPB, TPB>>>(counts, n_nodes);

    // 2) histogram rows
    hist_kernel<<<(n_edges + TPB - 1) / TPB, TPB>>>(adj_row, counts, n_edges);

    // 3) scan -> offsets (+cursor)
    scan_kernel<<<1, 1024>>>(counts, offs, cursor, n_nodes);

    // 4) permute edges into row-grouped order
    permute_kernel<<<(n_edges + TPB - 1) / TPB, TPB>>>(adj_row, adj_col, adj_val,
                                                       cursor, edges, n_edges);

    // 5) layer 1: learn1 = spmm(fea) + bias0   (warp per row, no atomics)
    {
        int blocks = (n_nodes * 32 + TPB - 1) / TPB;
        spmm_csr_kernel<0><<<blocks, TPB>>>((const float4*)fea, (float4*)learn1,
                                            offs, edges, (const float4*)bias,
                                            nullptr, n_nodes);
    }

    // 6) layer 2 + fused final: out = (fea + learn1 + spmm(learn1)+bias1)/3
    {
        int blocks = (n_nodes * 32 + TPB - 1) / TPB;
        spmm_csr_kernel<1><<<blocks, TPB>>>((const float4*)learn1, (float4*)out,
                                            offs, edges,
                                            (const float4*)(bias + HIDDEN),
                                            (const float4*)fea, n_nodes);
    }
}